// round 2
// baseline (speedup 1.0000x reference)
#include <cuda_runtime.h>
#include <math.h>

#define BB   2
#define NNN  2048
#define DIMM 1024
#define NH   16
#define HD   64
#define SCALE_ATT 0.125f   // 1/sqrt(64)
#define M_TOT (BB*NNN)     // 4096

// scratch (static device globals — no runtime allocation)
__device__ float g_qkv[(size_t)BB*NNN*3*DIMM];  // [B*N][3072]
__device__ float g_att[(size_t)BB*NNN*DIMM];    // [B*N][1024]

// ---------------------------------------------------------------------------
// Generic NT sgemm: C[M][Nn] = A[M][K] * W[Nn][K]^T (+ optional bias[Nn])
// 128x128 tile, BK=16, 256 threads, 8x8 strided micro-tile.
// ---------------------------------------------------------------------------
template<bool HAS_BIAS>
__global__ __launch_bounds__(256)
void sgemm_nt(const float* __restrict__ A, const float* __restrict__ W,
              const float* __restrict__ bias, float* __restrict__ C,
              int M, int Nn, int K)
{
    __shared__ float As[16][128];
    __shared__ float Bs[16][128];

    const int tid = threadIdx.x;
    const int tx = tid & 15, ty = tid >> 4;
    const int m0 = blockIdx.y * 128, n0 = blockIdx.x * 128;

    float acc[8][8];
#pragma unroll
    for (int i = 0; i < 8; i++)
#pragma unroll
        for (int j = 0; j < 8; j++) acc[i][j] = 0.f;

    for (int k0 = 0; k0 < K; k0 += 16) {
#pragma unroll
        for (int it = 0; it < 2; it++) {
            int idx = tid + it * 256;            // 0..511
            int m   = idx >> 2;                  // 0..127
            int k4  = (idx & 3) << 2;            // 0,4,8,12
            float4 va = *reinterpret_cast<const float4*>(
                &A[(size_t)(m0 + m) * K + k0 + k4]);
            As[k4 + 0][m] = va.x; As[k4 + 1][m] = va.y;
            As[k4 + 2][m] = va.z; As[k4 + 3][m] = va.w;
            float4 vb = *reinterpret_cast<const float4*>(
                &W[(size_t)(n0 + m) * K + k0 + k4]);
            Bs[k4 + 0][m] = vb.x; Bs[k4 + 1][m] = vb.y;
            Bs[k4 + 2][m] = vb.z; Bs[k4 + 3][m] = vb.w;
        }
        __syncthreads();
#pragma unroll
        for (int kk = 0; kk < 16; kk++) {
            float a[8], b[8];
#pragma unroll
            for (int i = 0; i < 8; i++) a[i] = As[kk][ty + 16 * i];
#pragma unroll
            for (int j = 0; j < 8; j++) b[j] = Bs[kk][tx + 16 * j];
#pragma unroll
            for (int i = 0; i < 8; i++)
#pragma unroll
                for (int j = 0; j < 8; j++)
                    acc[i][j] = fmaf(a[i], b[j], acc[i][j]);
        }
        __syncthreads();
    }

#pragma unroll
    for (int i = 0; i < 8; i++) {
        int m = m0 + ty + 16 * i;
#pragma unroll
        for (int j = 0; j < 8; j++) {
            int n = n0 + tx + 16 * j;
            float v = acc[i][j];
            if (HAS_BIAS) v += bias[n];
            C[(size_t)m * Nn + n] = v;
        }
    }
}

// ---------------------------------------------------------------------------
// Flash attention: one block per (b, h, 64-row q tile). 64x64 K/V tiles.
// 256 threads as 16x16, 4x4 micro-tiles (stride-16), online softmax.
// Dynamic smem: Qt[64][65] (d-major), KP[64*65] (Kt d-major, reused as Ps
// r-major), Vs[64][64].
// ---------------------------------------------------------------------------
__global__ __launch_bounds__(256)
void attn_kernel(const float* __restrict__ qkv, float* __restrict__ out)
{
    extern __shared__ float smem[];
    float* Qt = smem;              // 64*65
    float* KP = smem + 64 * 65;    // 64*65 (Kt, then Ps)
    float* Vs = KP + 64 * 65;      // 64*64

    const int tid = threadIdx.x;
    const int tx = tid & 15, ty = tid >> 4;
    const int qt = blockIdx.x, h = blockIdx.y, b = blockIdx.z;
    const size_t rstride = 3 * DIMM;
    const float* base = qkv + (size_t)b * NNN * rstride;
    const int q0 = qt * 64;

    // load Q tile, transposed to Qt[d][r]
    {
        int r0 = tid >> 4;             // 0..15
        int d4 = (tid & 15) << 2;      // 0..60
#pragma unroll
        for (int it = 0; it < 4; it++) {
            int rr = r0 + it * 16;
            float4 v = *reinterpret_cast<const float4*>(
                &base[(size_t)(q0 + rr) * rstride + h * HD + d4]);
            Qt[(d4 + 0) * 65 + rr] = v.x;
            Qt[(d4 + 1) * 65 + rr] = v.y;
            Qt[(d4 + 2) * 65 + rr] = v.z;
            Qt[(d4 + 3) * 65 + rr] = v.w;
        }
    }

    float m_r[4], l_r[4], o[4][4];
#pragma unroll
    for (int i = 0; i < 4; i++) {
        m_r[i] = -INFINITY;
        l_r[i] = 0.f;
#pragma unroll
        for (int j = 0; j < 4; j++) o[i][j] = 0.f;
    }

    for (int kt = 0; kt < NNN / 64; kt++) {
        const int k0 = kt * 64;
        __syncthreads();   // prior iter's reads of KP/Vs done (and Q load visible)
        // load K transposed (KP as Kt[d][c]) and V natural (Vs[c][d])
        {
            int r0 = tid >> 4;
            int d4 = (tid & 15) << 2;
#pragma unroll
            for (int it = 0; it < 4; it++) {
                int rr = r0 + it * 16;
                const float* krow =
                    &base[(size_t)(k0 + rr) * rstride + DIMM + h * HD];
                float4 kv = *reinterpret_cast<const float4*>(krow + d4);
                KP[(d4 + 0) * 65 + rr] = kv.x;
                KP[(d4 + 1) * 65 + rr] = kv.y;
                KP[(d4 + 2) * 65 + rr] = kv.z;
                KP[(d4 + 3) * 65 + rr] = kv.w;
                const float* vrow =
                    &base[(size_t)(k0 + rr) * rstride + 2 * DIMM + h * HD];
                float4 vv = *reinterpret_cast<const float4*>(vrow + d4);
                *reinterpret_cast<float4*>(&Vs[rr * 64 + d4]) = vv;
            }
        }
        __syncthreads();

        // S = (Q K^T) * scale : 4x4 per thread, rows r=ty+16i, cols c=tx+16j
        float s[4][4];
#pragma unroll
        for (int i = 0; i < 4; i++)
#pragma unroll
            for (int j = 0; j < 4; j++) s[i][j] = 0.f;
#pragma unroll
        for (int d = 0; d < 64; d++) {
            float a[4], bb[4];
#pragma unroll
            for (int i = 0; i < 4; i++) a[i] = Qt[d * 65 + ty + 16 * i];
#pragma unroll
            for (int j = 0; j < 4; j++) bb[j] = KP[d * 65 + tx + 16 * j];
#pragma unroll
            for (int i = 0; i < 4; i++)
#pragma unroll
                for (int j = 0; j < 4; j++)
                    s[i][j] = fmaf(a[i], bb[j], s[i][j]);
        }

        // online softmax update (per row i; reduce across the 16 tx lanes)
        float alpha[4];
#pragma unroll
        for (int i = 0; i < 4; i++) {
            float mm = -INFINITY;
#pragma unroll
            for (int j = 0; j < 4; j++) {
                s[i][j] *= SCALE_ATT;
                mm = fmaxf(mm, s[i][j]);
            }
#pragma unroll
            for (int off = 8; off >= 1; off >>= 1)
                mm = fmaxf(mm, __shfl_xor_sync(0xffffffffu, mm, off));
            float mnew = fmaxf(m_r[i], mm);
            alpha[i] = __expf(m_r[i] - mnew);
            m_r[i] = mnew;
            float sum = 0.f;
#pragma unroll
            for (int j = 0; j < 4; j++) {
                s[i][j] = __expf(s[i][j] - mnew);
                sum += s[i][j];
            }
#pragma unroll
            for (int off = 8; off >= 1; off >>= 1)
                sum += __shfl_xor_sync(0xffffffffu, sum, off);
            l_r[i] = l_r[i] * alpha[i] + sum;
#pragma unroll
            for (int j = 0; j < 4; j++) o[i][j] *= alpha[i];
        }

        __syncthreads();   // everyone done reading Kt before overwrite as Ps
#pragma unroll
        for (int i = 0; i < 4; i++)
#pragma unroll
            for (int j = 0; j < 4; j++)
                KP[(ty + 16 * i) * 65 + tx + 16 * j] = s[i][j];
        __syncthreads();

        // O += P @ V : rows r=ty+16i, dcols = tx+16j
#pragma unroll
        for (int c = 0; c < 64; c++) {
            float a[4], bb[4];
#pragma unroll
            for (int i = 0; i < 4; i++) a[i] = KP[(ty + 16 * i) * 65 + c];
#pragma unroll
            for (int j = 0; j < 4; j++) bb[j] = Vs[c * 64 + tx + 16 * j];
#pragma unroll
            for (int i = 0; i < 4; i++)
#pragma unroll
                for (int j = 0; j < 4; j++)
                    o[i][j] = fmaf(a[i], bb[j], o[i][j]);
        }
    }

    // normalize + write out[b, n, h*64 + d]
#pragma unroll
    for (int i = 0; i < 4; i++) {
        float inv = 1.f / l_r[i];
        int r = q0 + ty + 16 * i;
#pragma unroll
        for (int j = 0; j < 4; j++)
            out[((size_t)(b * NNN + r)) * DIMM + h * HD + tx + 16 * j] =
                o[i][j] * inv;
    }
}

// ---------------------------------------------------------------------------
extern "C" void kernel_launch(void* const* d_in, const int* in_sizes, int n_in,
                              void* d_out, int out_size)
{
    const float* x     = (const float*)d_in[0];
    const float* w_qkv = (const float*)d_in[1];
    const float* w_prj = (const float*)d_in[2];
    const float* b_prj = (const float*)d_in[3];
    float* out = (float*)d_out;

    float *qkv_ptr, *att_ptr;
    cudaGetSymbolAddress((void**)&qkv_ptr, g_qkv);
    cudaGetSymbolAddress((void**)&att_ptr, g_att);

    const int SMEM_ATTN = (64 * 65 * 2 + 64 * 64) * sizeof(float); // 49664 B
    cudaFuncSetAttribute(attn_kernel,
                         cudaFuncAttributeMaxDynamicSharedMemorySize,
                         SMEM_ATTN);

    // 1) QKV GEMM: [4096,1024] x [3072,1024]^T -> [4096,3072]
    {
        dim3 grid(3 * DIMM / 128, M_TOT / 128);
        sgemm_nt<false><<<grid, 256>>>(x, w_qkv, nullptr, qkv_ptr,
                                       M_TOT, 3 * DIMM, DIMM);
    }
    // 2) attention
    {
        dim3 grid(NNN / 64, NH, BB);
        attn_kernel<<<grid, 256, SMEM_ATTN>>>(qkv_ptr, att_ptr);
    }
    // 3) projection GEMM + bias: [4096,1024] x [1024,1024]^T -> [4096,1024]
    {
        dim3 grid(DIMM / 128, M_TOT / 128);
        sgemm_nt<true><<<grid, 256>>>(att_ptr, w_prj, b_prj, out,
                                      M_TOT, DIMM, DIMM);
    }
}

// round 5
// speedup vs baseline: 2.3234x; 2.3234x over previous
#include <cuda_runtime.h>
#include <math.h>
#include <stdint.h>

#define BB   2
#define NNN  2048
#define DIMM 1024
#define NH   16
#define HD   64
#define M_TOT (BB*NNN)     // 4096

// scratch (static device globals — no runtime allocation)
__device__ float g_qkv[(size_t)BB*NNN*3*DIMM];   // [B*N][3072] (tf32-rounded)
__device__ float g_att[(size_t)BB*NNN*DIMM];     // [B*N][1024] (tf32-rounded)
__device__ float g_xr[(size_t)M_TOT*DIMM];       // x rounded to tf32
__device__ float g_wqkvr[(size_t)3*DIMM*DIMM];   // w_qkv rounded
__device__ float g_wprjr[(size_t)DIMM*DIMM];     // w_prj rounded

// ---------------------------------------------------------------------------
// helpers
// ---------------------------------------------------------------------------
__device__ __forceinline__ uint32_t smem_u32(const void* p) {
    uint32_t r;
    asm("{ .reg .u64 t; cvta.to.shared.u64 t, %1; cvt.u32.u64 %0, t; }"
        : "=r"(r) : "l"(p));
    return r;
}

__device__ __forceinline__ float rna_tf32(float x) {
    float r;
    asm("cvt.rna.tf32.f32 %0, %1;" : "=f"(r) : "f"(x));
    return r;
}

__device__ __forceinline__ void mma_tf32(float* c, const uint32_t* a,
                                         const uint32_t* b) {
    asm volatile(
        "mma.sync.aligned.m16n8k8.row.col.f32.tf32.tf32.f32 "
        "{%0,%1,%2,%3}, {%4,%5,%6,%7}, {%8,%9}, {%0,%1,%2,%3};"
        : "+f"(c[0]), "+f"(c[1]), "+f"(c[2]), "+f"(c[3])
        : "r"(a[0]), "r"(a[1]), "r"(a[2]), "r"(a[3]),
          "r"(b[0]), "r"(b[1]));
}

#define CP16(dst, src) \
    asm volatile("cp.async.cg.shared.global [%0], [%1], 16;" :: "r"(dst), "l"(src))
#define CP_COMMIT() asm volatile("cp.async.commit_group;" ::: "memory")
#define CP_WAIT2()  asm volatile("cp.async.wait_group 2;" ::: "memory")

// ---------------------------------------------------------------------------
// tf32 pre-round: out[i] = rna_tf32(in[i])   (all sizes divisible by 1024)
// ---------------------------------------------------------------------------
__global__ __launch_bounds__(256)
void round_tf32_kernel(const float* __restrict__ in, float* __restrict__ out,
                       int n)
{
    int i = (blockIdx.x * 256 + threadIdx.x) * 4;
    if (i < n) {
        float4 v = *reinterpret_cast<const float4*>(in + i);
        v.x = rna_tf32(v.x); v.y = rna_tf32(v.y);
        v.z = rna_tf32(v.z); v.w = rna_tf32(v.w);
        *reinterpret_cast<float4*>(out + i) = v;
    }
}

// ---------------------------------------------------------------------------
// tf32 mma.sync GEMM:  C[M][Nn] = A[M][K] * W[Nn][K]^T (+bias) (opt rna out)
// 128x128 tile, BK=16, 3-stage cp.async, 256 threads (8 warps, 2m x 4n).
// smem per stage: A 128x20 floats + B 128x20 floats = 20480 B; 3 stages.
// ---------------------------------------------------------------------------
#define GLD 20                       // padded floats per smem row
#define GSTAGE_F (2 * 128 * GLD)     // floats per stage (A+B) = 5120
#define GSMEM_TOTAL (3 * GSTAGE_F * 4)   // 61440 bytes

template<bool HAS_BIAS, bool ROUND_OUT>
__global__ __launch_bounds__(256, 2)
void gemm_tf32(const float* __restrict__ A, const float* __restrict__ W,
               const float* __restrict__ bias, float* __restrict__ C,
               int M, int Nn, int K)
{
    extern __shared__ float smf[];
    const uint32_t sbase = smem_u32(smf);
    const int tid = threadIdx.x;
    const int wid = tid >> 5, lane = tid & 31;
    const int gid = lane >> 2, tig = lane & 3;     // groupID, threadID_in_group
    const int wm = wid & 1, wn = wid >> 1;         // warp 64m x 32n
    const int m0 = blockIdx.y * 128, n0 = blockIdx.x * 128;
    const int NK = K >> 4;

    float acc[4][4][4];
#pragma unroll
    for (int mi = 0; mi < 4; mi++)
#pragma unroll
        for (int ni = 0; ni < 4; ni++)
#pragma unroll
            for (int q = 0; q < 4; q++) acc[mi][ni][q] = 0.f;

    auto load_stage = [&](int s, int kt) {
        uint32_t sa = sbase + s * (GSTAGE_F * 4);
        uint32_t sb = sa + 128 * GLD * 4;
        int k0 = kt << 4;
#pragma unroll
        for (int t = 0; t < 2; t++) {
            int idx = tid + t * 256;
            int row = idx >> 2, ch = idx & 3;
            CP16(sa + row * (GLD * 4) + ch * 16,
                 A + (size_t)(m0 + row) * K + k0 + ch * 4);
            CP16(sb + row * (GLD * 4) + ch * 16,
                 W + (size_t)(n0 + row) * K + k0 + ch * 4);
        }
        CP_COMMIT();
    };

    // prologue: tiles 0,1 into slots 0,1
    load_stage(0, 0);
    load_stage(1, 1);

    for (int kt = 0; kt < NK; kt++) {
        __syncthreads();                      // everyone done computing kt-1
        if (kt + 2 < NK) load_stage((kt + 2) % 3, kt + 2);
        else CP_COMMIT();                     // empty group, keeps counts
        CP_WAIT2();                           // tile kt landed (this thread)
        __syncthreads();                      // ... and every thread's

        const float* As = smf + (kt % 3) * GSTAGE_F;
        const float* Bs = As + 128 * GLD;
#pragma unroll
        for (int ks = 0; ks < 2; ks++) {
            const int kc = ks * 8;
            uint32_t a[4][4], b[4][2];
#pragma unroll
            for (int mi = 0; mi < 4; mi++) {
                int r = wm * 64 + mi * 16 + gid;
                a[mi][0] = __float_as_uint(As[r * GLD + kc + tig]);
                a[mi][1] = __float_as_uint(As[(r + 8) * GLD + kc + tig]);
                a[mi][2] = __float_as_uint(As[r * GLD + kc + tig + 4]);
                a[mi][3] = __float_as_uint(As[(r + 8) * GLD + kc + tig + 4]);
            }
#pragma unroll
            for (int ni = 0; ni < 4; ni++) {
                int n = wn * 32 + ni * 8 + gid;
                b[ni][0] = __float_as_uint(Bs[n * GLD + kc + tig]);
                b[ni][1] = __float_as_uint(Bs[n * GLD + kc + tig + 4]);
            }
#pragma unroll
            for (int mi = 0; mi < 4; mi++)
#pragma unroll
                for (int ni = 0; ni < 4; ni++)
                    mma_tf32(acc[mi][ni], a[mi], b[ni]);
        }
    }

    // epilogue
#pragma unroll
    for (int mi = 0; mi < 4; mi++) {
        int r = m0 + wm * 64 + mi * 16 + gid;
#pragma unroll
        for (int ni = 0; ni < 4; ni++) {
            int c = n0 + wn * 32 + ni * 8 + tig * 2;
            float v0 = acc[mi][ni][0], v1 = acc[mi][ni][1];
            float v2 = acc[mi][ni][2], v3 = acc[mi][ni][3];
            if (HAS_BIAS) {
                float b0 = __ldg(&bias[c]), b1 = __ldg(&bias[c + 1]);
                v0 += b0; v1 += b1; v2 += b0; v3 += b1;
            }
            if (ROUND_OUT) {
                v0 = rna_tf32(v0); v1 = rna_tf32(v1);
                v2 = rna_tf32(v2); v3 = rna_tf32(v3);
            }
            *reinterpret_cast<float2*>(&C[(size_t)r * Nn + c]) =
                make_float2(v0, v1);
            *reinterpret_cast<float2*>(&C[(size_t)(r + 8) * Nn + c]) =
                make_float2(v2, v3);
        }
    }
}

// ---------------------------------------------------------------------------
// Flash attention on mma.sync tf32. Block = (b, h, 64-row q tile), 4 warps.
// Warp w owns q rows [16w, 16w+16). K/V tiles of 64. smem ld = 68 floats.
// Qs pre-scaled by 0.125 (exact in tf32). qkv already tf32-rounded.
// ---------------------------------------------------------------------------
#define ALD 68
#define ATTN_SMEM (4 * 64 * ALD * 4)   // Qs, Ks, Vt, Ps = 69632 B

__global__ __launch_bounds__(128)
void attn_mma_kernel(const float* __restrict__ qkv, float* __restrict__ out)
{
    extern __shared__ float smf[];
    float* Qs = smf;                 // [64][68]  q rows (scaled)
    float* Ks = smf + 64 * ALD;      // [64][68]  k rows
    float* Vt = smf + 2 * 64 * ALD;  // [68*64]   v transposed: [d][seq]
    float* Ps = smf + 3 * 64 * ALD;  // [64][68]  probabilities

    const int tid = threadIdx.x;
    const int w = tid >> 5, lane = tid & 31;
    const int gid = lane >> 2, tig = lane & 3;
    const int qt = blockIdx.x, h = blockIdx.y, b = blockIdx.z;
    const int q0 = qt * 64;
    const float* base = qkv + (size_t)b * NNN * (3 * DIMM);

    // load Q tile (scaled by 2^-3, exact)
    {
        int r = tid >> 1, half = tid & 1;
        const float* src = base + (size_t)(q0 + r) * (3 * DIMM) + h * HD + half * 32;
        float* dst = Qs + r * ALD + half * 32;
#pragma unroll
        for (int i = 0; i < 8; i++) {
            float4 v = *reinterpret_cast<const float4*>(src + i * 4);
            dst[i * 4 + 0] = v.x * 0.125f;
            dst[i * 4 + 1] = v.y * 0.125f;
            dst[i * 4 + 2] = v.z * 0.125f;
            dst[i * 4 + 3] = v.w * 0.125f;
        }
    }

    float o[8][4];                      // O tile 16x64 per warp
    float mA = -INFINITY, mB = -INFINITY, lA = 0.f, lB = 0.f;
#pragma unroll
    for (int ni = 0; ni < 8; ni++)
#pragma unroll
        for (int q = 0; q < 4; q++) o[ni][q] = 0.f;

    for (int kt = 0; kt < NNN / 64; kt++) {
        const int k0 = kt * 64;
        __syncthreads();     // prev iter's mma reads of Ks/Vt complete
        // load K rows + V transposed
        {
            int r = tid >> 1, half = tid & 1;
            const float* ksrc =
                base + (size_t)(k0 + r) * (3 * DIMM) + DIMM + h * HD + half * 32;
            float* kdst = Ks + r * ALD + half * 32;
            const float* vsrc =
                base + (size_t)(k0 + r) * (3 * DIMM) + 2 * DIMM + h * HD + half * 32;
#pragma unroll
            for (int i = 0; i < 8; i++) {
                float4 kv = *reinterpret_cast<const float4*>(ksrc + i * 4);
                *reinterpret_cast<float4*>(kdst + i * 4) = kv;
                float4 vv = *reinterpret_cast<const float4*>(vsrc + i * 4);
                int d = half * 32 + i * 4;
                Vt[(d + 0) * ALD + r] = vv.x;
                Vt[(d + 1) * ALD + r] = vv.y;
                Vt[(d + 2) * ALD + r] = vv.z;
                Vt[(d + 3) * ALD + r] = vv.w;
            }
        }
        __syncthreads();

        // ---- S = Q K^T (scale folded into Q) ----
        float s[8][4];
#pragma unroll
        for (int ni = 0; ni < 8; ni++)
#pragma unroll
            for (int q = 0; q < 4; q++) s[ni][q] = 0.f;
#pragma unroll
        for (int ks = 0; ks < 8; ks++) {
            const int kc = ks * 8;
            uint32_t a[4], bf[8][2];
            int r = w * 16 + gid;
            a[0] = __float_as_uint(Qs[r * ALD + kc + tig]);
            a[1] = __float_as_uint(Qs[(r + 8) * ALD + kc + tig]);
            a[2] = __float_as_uint(Qs[r * ALD + kc + tig + 4]);
            a[3] = __float_as_uint(Qs[(r + 8) * ALD + kc + tig + 4]);
#pragma unroll
            for (int ni = 0; ni < 8; ni++) {
                int n = ni * 8 + gid;
                bf[ni][0] = __float_as_uint(Ks[n * ALD + kc + tig]);
                bf[ni][1] = __float_as_uint(Ks[n * ALD + kc + tig + 4]);
            }
#pragma unroll
            for (int ni = 0; ni < 8; ni++) mma_tf32(s[ni], a, bf[ni]);
        }

        // ---- online softmax (rows: rA = gid, rB = gid+8, 4-lane groups) ----
        float tmaxA = -INFINITY, tmaxB = -INFINITY;
#pragma unroll
        for (int ni = 0; ni < 8; ni++) {
            tmaxA = fmaxf(tmaxA, fmaxf(s[ni][0], s[ni][1]));
            tmaxB = fmaxf(tmaxB, fmaxf(s[ni][2], s[ni][3]));
        }
        tmaxA = fmaxf(tmaxA, __shfl_xor_sync(0xffffffffu, tmaxA, 1));
        tmaxA = fmaxf(tmaxA, __shfl_xor_sync(0xffffffffu, tmaxA, 2));
        tmaxB = fmaxf(tmaxB, __shfl_xor_sync(0xffffffffu, tmaxB, 1));
        tmaxB = fmaxf(tmaxB, __shfl_xor_sync(0xffffffffu, tmaxB, 2));
        float mAn = fmaxf(mA, tmaxA), mBn = fmaxf(mB, tmaxB);
        float alphaA = __expf(mA - mAn), alphaB = __expf(mB - mBn);
        mA = mAn; mB = mBn;
        float sumA = 0.f, sumB = 0.f;
#pragma unroll
        for (int ni = 0; ni < 8; ni++) {
            s[ni][0] = __expf(s[ni][0] - mAn);
            s[ni][1] = __expf(s[ni][1] - mAn);
            s[ni][2] = __expf(s[ni][2] - mBn);
            s[ni][3] = __expf(s[ni][3] - mBn);
            sumA += s[ni][0] + s[ni][1];
            sumB += s[ni][2] + s[ni][3];
        }
        sumA += __shfl_xor_sync(0xffffffffu, sumA, 1);
        sumA += __shfl_xor_sync(0xffffffffu, sumA, 2);
        sumB += __shfl_xor_sync(0xffffffffu, sumB, 1);
        sumB += __shfl_xor_sync(0xffffffffu, sumB, 2);
        lA = lA * alphaA + sumA;
        lB = lB * alphaB + sumB;
#pragma unroll
        for (int ni = 0; ni < 8; ni++) {
            o[ni][0] *= alphaA; o[ni][1] *= alphaA;
            o[ni][2] *= alphaB; o[ni][3] *= alphaB;
        }

        // ---- P to warp-private smem rows (rna for tf32 mma) ----
        {
            int rA = w * 16 + gid, rB = rA + 8;
#pragma unroll
            for (int ni = 0; ni < 8; ni++) {
                int c = ni * 8 + tig * 2;
                *reinterpret_cast<float2*>(&Ps[rA * ALD + c]) =
                    make_float2(rna_tf32(s[ni][0]), rna_tf32(s[ni][1]));
                *reinterpret_cast<float2*>(&Ps[rB * ALD + c]) =
                    make_float2(rna_tf32(s[ni][2]), rna_tf32(s[ni][3]));
            }
        }
        __syncwarp();

        // ---- O += P V ----
#pragma unroll
        for (int ks = 0; ks < 8; ks++) {
            const int kc = ks * 8;
            uint32_t a[4], bf[8][2];
            int r = w * 16 + gid;
            a[0] = __float_as_uint(Ps[r * ALD + kc + tig]);
            a[1] = __float_as_uint(Ps[(r + 8) * ALD + kc + tig]);
            a[2] = __float_as_uint(Ps[r * ALD + kc + tig + 4]);
            a[3] = __float_as_uint(Ps[(r + 8) * ALD + kc + tig + 4]);
#pragma unroll
            for (int ni = 0; ni < 8; ni++) {
                int d = ni * 8 + gid;
                bf[ni][0] = __float_as_uint(Vt[d * ALD + kc + tig]);
                bf[ni][1] = __float_as_uint(Vt[d * ALD + kc + tig + 4]);
            }
#pragma unroll
            for (int ni = 0; ni < 8; ni++) mma_tf32(o[ni], a, bf[ni]);
        }
    }

    // normalize + write (rna for the tf32 projection GEMM)
    {
        float invA = 1.f / lA, invB = 1.f / lB;
        int rA = b * NNN + q0 + w * 16 + gid;
#pragma unroll
        for (int ni = 0; ni < 8; ni++) {
            int c = h * HD + ni * 8 + tig * 2;
            *reinterpret_cast<float2*>(&out[(size_t)rA * DIMM + c]) =
                make_float2(rna_tf32(o[ni][0] * invA), rna_tf32(o[ni][1] * invA));
            *reinterpret_cast<float2*>(&out[(size_t)(rA + 8) * DIMM + c]) =
                make_float2(rna_tf32(o[ni][2] * invB), rna_tf32(o[ni][3] * invB));
        }
    }
}

// ---------------------------------------------------------------------------
extern "C" void kernel_launch(void* const* d_in, const int* in_sizes, int n_in,
                              void* d_out, int out_size)
{
    const float* x     = (const float*)d_in[0];
    const float* w_qkv = (const float*)d_in[1];
    const float* w_prj = (const float*)d_in[2];
    const float* b_prj = (const float*)d_in[3];
    float* out = (float*)d_out;

    float *qkv_p, *att_p, *xr_p, *wqkvr_p, *wprjr_p;
    cudaGetSymbolAddress((void**)&qkv_p,  g_qkv);
    cudaGetSymbolAddress((void**)&att_p,  g_att);
    cudaGetSymbolAddress((void**)&xr_p,   g_xr);
    cudaGetSymbolAddress((void**)&wqkvr_p, g_wqkvr);
    cudaGetSymbolAddress((void**)&wprjr_p, g_wprjr);

    cudaFuncSetAttribute(gemm_tf32<false, true>,
                         cudaFuncAttributeMaxDynamicSharedMemorySize, GSMEM_TOTAL);
    cudaFuncSetAttribute(gemm_tf32<true, false>,
                         cudaFuncAttributeMaxDynamicSharedMemorySize, GSMEM_TOTAL);
    cudaFuncSetAttribute(attn_mma_kernel,
                         cudaFuncAttributeMaxDynamicSharedMemorySize, ATTN_SMEM);

    // 0) pre-round inputs to tf32 (zero-mean rounding for the HMMAs)
    {
        int nx = M_TOT * DIMM, nq = 3 * DIMM * DIMM, np = DIMM * DIMM;
        round_tf32_kernel<<<nx / 1024, 256>>>(x, xr_p, nx);
        round_tf32_kernel<<<nq / 1024, 256>>>(w_qkv, wqkvr_p, nq);
        round_tf32_kernel<<<np / 1024, 256>>>(w_prj, wprjr_p, np);
    }
    // 1) QKV GEMM: [4096,1024] x [3072,1024]^T -> [4096,3072] (rounded out)
    {
        dim3 grid(3 * DIMM / 128, M_TOT / 128);
        gemm_tf32<false, true><<<grid, 256, GSMEM_TOTAL>>>(
            xr_p, wqkvr_p, nullptr, qkv_p, M_TOT, 3 * DIMM, DIMM);
    }
    // 2) attention (mma.sync tf32 flash)
    {
        dim3 grid(NNN / 64, NH, BB);
        attn_mma_kernel<<<grid, 128, ATTN_SMEM>>>(qkv_p, att_p);
    }
    // 3) projection GEMM + bias: [4096,1024] x [1024,1024]^T -> [4096,1024]
    {
        dim3 grid(DIMM / 128, M_TOT / 128);
        gemm_tf32<true, false><<<grid, 256, GSMEM_TOTAL>>>(
            att_p, wprjr_p, b_prj, out, M_TOT, DIMM, DIMM);
    }
}